// round 8
// baseline (speedup 1.0000x reference)
#include <cuda_runtime.h>

#define NN 100000
#define NE 1600000
#define CH 64
#define NG 64
#define SCAN_BS 1024
#define SCAN_NB ((NN + SCAN_BS - 1) / SCAN_BS)   // 98
#define TILE_N 128                                // nodes per node-kernel block
#define APAD 132                                  // At row stride: 528B, 16B-aligned
#define WCH 16                                    // k-rows per W chunk
#define WPAD 66                                   // Wd row stride in ull (528B)

typedef unsigned long long ull;

// ---------------- device scratch (no allocation allowed) ----------------
__device__ __align__(16) float g_agg[NN * CH];
__device__ __align__(16) float g_h0[NN * CH];
__device__ __align__(16) float g_h1[NN * CH];
__device__ float g_inv[NN];
__device__ int   g_deg[NN];
__device__ int   g_off[NN];
__device__ int   g_fill[NN];
__device__ int   g_srcl[NE];
__device__ int   g_bsum[SCAN_NB];
__device__ float g_pool[NG * CH];
__device__ float g_pcnt[NG];
__device__ int   g_is64_ei;
__device__ int   g_is64_b;

// ---------------- f32x2 helpers ----------------
__device__ __forceinline__ ull pack2(float a) {
    ull r; unsigned int u = __float_as_uint(a);
    asm("mov.b64 %0, {%1, %2};" : "=l"(r) : "r"(u), "r"(u));
    return r;
}
__device__ __forceinline__ void fma2(ull& d, ull a, ull b) {
    asm("fma.rn.f32x2 %0, %1, %2, %3;" : "=l"(d) : "l"(a), "l"(b), "l"(d));
}
__device__ __forceinline__ float f2lo(ull v) { return __uint_as_float((unsigned int)v); }
__device__ __forceinline__ float f2hi(ull v) { return __uint_as_float((unsigned int)(v >> 32)); }

// ---------------- init: zero deg/pool + dtype detect ----------------
__global__ void init_kernel(const int* __restrict__ ei32, const int* __restrict__ b32) {
    int i = blockIdx.x * blockDim.x + threadIdx.x;
    if (i < NN) g_deg[i] = 0;
    if (blockIdx.x == 0) {
        for (int j = threadIdx.x; j < NG * CH; j += blockDim.x) g_pool[j] = 0.f;
        if (threadIdx.x < NG) g_pcnt[threadIdx.x] = 0.f;
        if (threadIdx.x == 0) {
            int oe = 0, ob = 0;
#pragma unroll 1
            for (int t = 0; t < 64; t++) oe |= ei32[2 * (t * 24999 + 7) + 1];
#pragma unroll 1
            for (int t = 0; t < 64; t++) ob |= b32[2 * (t * 780 + 3) + 1];
            g_is64_ei = (oe == 0) ? 1 : 0;
            g_is64_b  = (ob == 0) ? 1 : 0;
        }
    }
}

// ---------------- CSR build ----------------
__global__ void deg_kernel(const int* __restrict__ ei) {
    int e = blockIdx.x * blockDim.x + threadIdx.x;
    if (e < NE) {
        int d = g_is64_ei ? ei[2 * (NE + e)] : ei[NE + e];
        atomicAdd(&g_deg[d], 1);
    }
}
__global__ void scan1_kernel() {
    __shared__ int s[SCAN_BS];
    int t = threadIdx.x;
    int gid = blockIdx.x * SCAN_BS + t;
    int v = (gid < NN) ? g_deg[gid] : 0;
    s[t] = v;
    __syncthreads();
    for (int off = 1; off < SCAN_BS; off <<= 1) {
        int x = (t >= off) ? s[t - off] : 0;
        __syncthreads();
        s[t] += x;
        __syncthreads();
    }
    if (gid < NN) g_off[gid] = s[t] - v;
    if (t == SCAN_BS - 1) g_bsum[blockIdx.x] = s[t];
}
__global__ void scan2b_kernel() {
    __shared__ int s[128];
    __shared__ int base_s;
    int t = threadIdx.x;
    if (t < 128) s[t] = (t < (int)blockIdx.x && t < SCAN_NB) ? g_bsum[t] : 0;
    __syncthreads();
    if (t < 64) s[t] += s[t + 64];
    __syncthreads();
    if (t < 32) {
        int v = s[t] + s[t + 32];
        for (int o = 16; o > 0; o >>= 1) v += __shfl_down_sync(0xffffffffu, v, o);
        if (t == 0) base_s = v;
    }
    __syncthreads();
    int gid = blockIdx.x * SCAN_BS + t;
    if (gid < NN) {
        int o = g_off[gid] + base_s;
        g_off[gid] = o;
        g_fill[gid] = o;
        g_inv[gid] = 1.0f / fmaxf((float)g_deg[gid], 1.0f);
    }
}
__global__ void fill_kernel(const int* __restrict__ ei) {
    int e = blockIdx.x * blockDim.x + threadIdx.x;
    if (e < NE) {
        int is64 = g_is64_ei;
        int s = is64 ? ei[2 * e]        : ei[e];
        int d = is64 ? ei[2 * (NE + e)] : ei[NE + e];
        g_srcl[atomicAdd(&g_fill[d], 1)] = s;
    }
}

// ---------------- aggregation via gather (R2-proven) ----------------
__global__ void __launch_bounds__(256) gather_kernel(const float* __restrict__ Xext,
                                                     int srcsel) {
    const float* __restrict__ X = (srcsel == 0) ? Xext : (srcsel == 1 ? g_h0 : g_h1);
    int warp = (blockIdx.x * blockDim.x + threadIdx.x) >> 5;
    int lane = threadIdx.x & 31;
    if (warp >= NN) return;
    int beg = g_off[warp];
    int deg = g_deg[warp];
    float a0 = 0.f, a1 = 0.f;
    int j = 0;
    for (; j + 2 <= deg; j += 2) {
        int s0 = g_srcl[beg + j];
        int s1 = g_srcl[beg + j + 1];
        const float* r0 = X + (size_t)s0 * CH;
        const float* r1 = X + (size_t)s1 * CH;
        a0 += r0[lane] + r1[lane];
        a1 += r0[lane + 32] + r1[lane + 32];
    }
    if (j < deg) {
        const float* r0 = X + (size_t)g_srcl[beg + j] * CH;
        a0 += r0[lane];
        a1 += r0[lane + 32];
    }
    float iv = g_inv[warp];
    g_agg[(size_t)warp * CH + lane]      = a0 * iv;
    g_agg[(size_t)warp * CH + lane + 32] = a1 * iv;
}

// ---------------- node transform: f32x2 GEMM ----------------
// Y = relu( agg @ Wl + b + X @ Wr ). TILE_N=128 nodes, 256 threads.
// At[k][node] transposed (aligned rows); W staged DUPLICATED as ull (zero packs
// in inner loop). Micro-tile: 8 nodes (4 f32x2 pairs) x 4 cols = 16 FFMA2/k.
__global__ void __launch_bounds__(256) node_kernel(const float* __restrict__ Xext,
                                                   const float* __restrict__ Wl,
                                                   const float* __restrict__ bvec,
                                                   const float* __restrict__ Wr,
                                                   int srcsel, int dstsel) {
    const float* __restrict__ Xin = (srcsel == 0) ? Xext : (srcsel == 1 ? g_h0 : g_h1);
    float* __restrict__ Yout = (dstsel == 1) ? g_h0 : g_h1;

    __shared__ __align__(16) float At[64][APAD];  // 33.8 KB
    __shared__ __align__(16) ull   Wd[WCH][WPAD]; // 8.25 KB (duplicated W chunk)
    __shared__ float bs[64];

    int tid = threadIdx.x;
    int nbase = blockIdx.x * TILE_N;
    int tx = tid & 15;    // node group: nodes 8*tx .. 8*tx+7
    int ty = tid >> 4;    // col group:  cols 4*ty .. 4*ty+3

    if (tid < 64) bs[tid] = bvec[tid];

    ull acc[4][4];        // [node-pair][col]
#pragma unroll
    for (int p = 0; p < 4; p++)
#pragma unroll
        for (int c = 0; c < 4; c++) acc[p][c] = 0ull;

    // ---- stage At <- agg (transposed, coalesced reads) ----
    {
        int nn = tid >> 4;            // 0..15
        int k4 = (tid & 15) * 4;      // 0..60
#pragma unroll
        for (int r = 0; r < TILE_N; r += 16) {
            int n = nbase + nn + r;
            float4 v = make_float4(0.f, 0.f, 0.f, 0.f);
            if (n < NN) v = *(const float4*)&g_agg[(size_t)n * CH + k4];
            At[k4 + 0][nn + r] = v.x;
            At[k4 + 1][nn + r] = v.y;
            At[k4 + 2][nn + r] = v.z;
            At[k4 + 3][nn + r] = v.w;
        }
    }

    // ---- GEMM over both matrices; m=0: agg@Wl, m=1: X@Wr ----
#pragma unroll 1
    for (int m = 0; m < 2; m++) {
        const float* __restrict__ W = (m == 0) ? Wl : Wr;
#pragma unroll 1
        for (int cchunk = 0; cchunk < 64 / WCH; cchunk++) {
            __syncthreads();   // At staged / prev chunk consumed
            for (int i = tid; i < WCH * 64; i += 256) {
                int k = i >> 6, col = i & 63;
                Wd[k][col] = pack2(W[(cchunk * WCH + k) * 64 + col]);
            }
            __syncthreads();
#pragma unroll
            for (int kk = 0; kk < WCH; kk++) {
                int k = cchunk * WCH + kk;
                ulonglong2 aA = *(const ulonglong2*)&At[k][tx * 8];
                ulonglong2 aB = *(const ulonglong2*)&At[k][tx * 8 + 4];
                ulonglong2 wA = *(const ulonglong2*)&Wd[kk][ty * 4];
                ulonglong2 wB = *(const ulonglong2*)&Wd[kk][ty * 4 + 2];
                ull av[4] = {aA.x, aA.y, aB.x, aB.y};
                ull wv[4] = {wA.x, wA.y, wB.x, wB.y};
#pragma unroll
                for (int p = 0; p < 4; p++) {
                    fma2(acc[p][0], av[p], wv[0]);
                    fma2(acc[p][1], av[p], wv[1]);
                    fma2(acc[p][2], av[p], wv[2]);
                    fma2(acc[p][3], av[p], wv[3]);
                }
            }
        }
        // restage At <- X for second pass
        if (m == 0) {
            __syncthreads();
            int nn = tid >> 4;
            int k4 = (tid & 15) * 4;
#pragma unroll
            for (int r = 0; r < TILE_N; r += 16) {
                int n = nbase + nn + r;
                float4 v = make_float4(0.f, 0.f, 0.f, 0.f);
                if (n < NN) v = *(const float4*)&Xin[(size_t)n * CH + k4];
                At[k4 + 0][nn + r] = v.x;
                At[k4 + 1][nn + r] = v.y;
                At[k4 + 2][nn + r] = v.z;
                At[k4 + 3][nn + r] = v.w;
            }
        }
    }

    // ---- epilogue: unpack pairs, bias + relu, float4 stores ----
    float4 bv = *(const float4*)&bs[ty * 4];
#pragma unroll
    for (int p = 0; p < 4; p++) {
        int n0 = nbase + tx * 8 + 2 * p;
        if (n0 < NN) {
            float4 o;
            o.x = fmaxf(f2lo(acc[p][0]) + bv.x, 0.f);
            o.y = fmaxf(f2lo(acc[p][1]) + bv.y, 0.f);
            o.z = fmaxf(f2lo(acc[p][2]) + bv.z, 0.f);
            o.w = fmaxf(f2lo(acc[p][3]) + bv.w, 0.f);
            *(float4*)&Yout[(size_t)n0 * CH + ty * 4] = o;
        }
        if (n0 + 1 < NN) {
            float4 o;
            o.x = fmaxf(f2hi(acc[p][0]) + bv.x, 0.f);
            o.y = fmaxf(f2hi(acc[p][1]) + bv.y, 0.f);
            o.z = fmaxf(f2hi(acc[p][2]) + bv.z, 0.f);
            o.w = fmaxf(f2hi(acc[p][3]) + bv.w, 0.f);
            *(float4*)&Yout[(size_t)(n0 + 1) * CH + ty * 4] = o;
        }
    }
}

// ---------------- pooling (batch is sorted) ----------------
__global__ void __launch_bounds__(256) pool_kernel(const int* __restrict__ batch) {
    int is64 = g_is64_b;
    const float* H = g_h0;   // final layer output lives in g_h0
    int c = threadIdx.x & 63;
    int rg = threadIdx.x >> 6;
    int r0 = blockIdx.x * 256 + rg * 64;
    float acc = 0.f, cacc = 0.f;
    int cur = -1;
    for (int i = 0; i < 64; i++) {
        int r = r0 + i;
        if (r >= NN) break;
        int g = is64 ? batch[2 * r] : batch[r];
        if (g != cur) {
            if (cur >= 0) {
                atomicAdd(&g_pool[cur * CH + c], acc);
                if (c == 0) atomicAdd(&g_pcnt[cur], cacc);
            }
            cur = g; acc = 0.f; cacc = 0.f;
        }
        acc += H[(size_t)r * CH + c];
        cacc += 1.f;
    }
    if (cur >= 0) {
        atomicAdd(&g_pool[cur * CH + c], acc);
        if (c == 0) atomicAdd(&g_pcnt[cur], cacc);
    }
}

// ---------------- MLP head ----------------
__global__ void head_kernel(const float* __restrict__ Wc1, const float* __restrict__ bc1,
                            const float* __restrict__ Wc2, const float* __restrict__ bc2,
                            float* __restrict__ out) {
    int g = threadIdx.x;
    if (g >= NG) return;
    float iv = 1.0f / fmaxf(g_pcnt[g], 1.0f);
    float gv[64];
#pragma unroll
    for (int k = 0; k < 64; k++) gv[k] = g_pool[g * CH + k] * iv;
    float o0 = bc2[0], o1 = bc2[1];
    for (int j = 0; j < 32; j++) {
        float h = bc1[j];
#pragma unroll
        for (int k = 0; k < 64; k++) h += gv[k] * Wc1[k * 32 + j];
        h = fmaxf(h, 0.f);
        o0 += h * Wc2[j * 2 + 0];
        o1 += h * Wc2[j * 2 + 1];
    }
    out[g * 2 + 0] = o0;
    out[g * 2 + 1] = o1;
}

extern "C" void kernel_launch(void* const* d_in, const int* in_sizes, int n_in,
                              void* d_out, int out_size) {
    (void)in_sizes; (void)n_in; (void)out_size;
    const float* x   = (const float*)d_in[0];
    const int* ei    = (const int*)d_in[1];    // width auto-detected on device
    const int* batch = (const int*)d_in[2];
    const float* W1l = (const float*)d_in[3];
    const float* b1  = (const float*)d_in[4];
    const float* W1r = (const float*)d_in[5];
    const float* W2l = (const float*)d_in[6];
    const float* b2  = (const float*)d_in[7];
    const float* W2r = (const float*)d_in[8];
    const float* W3l = (const float*)d_in[9];
    const float* b3  = (const float*)d_in[10];
    const float* W3r = (const float*)d_in[11];
    const float* Wc1 = (const float*)d_in[12];
    const float* bc1 = (const float*)d_in[13];
    const float* Wc2 = (const float*)d_in[14];
    const float* bc2 = (const float*)d_in[15];
    float* out = (float*)d_out;

    const int ZB = 256;
    const int gather_blocks = (NN * 32 + 255) / 256;       // warp per node
    const int node_blocks   = (NN + TILE_N - 1) / TILE_N;  // 782

    // CSR build (5 launches)
    init_kernel<<<(NN + ZB - 1) / ZB, ZB>>>(ei, batch);
    deg_kernel<<<(NE + ZB - 1) / ZB, ZB>>>(ei);
    scan1_kernel<<<SCAN_NB, SCAN_BS>>>();
    scan2b_kernel<<<SCAN_NB, SCAN_BS>>>();
    fill_kernel<<<(NE + ZB - 1) / ZB, ZB>>>(ei);

    // layer 1: x -> h0
    gather_kernel<<<gather_blocks, 256>>>(x, 0);
    node_kernel<<<node_blocks, 256>>>(x, W1l, b1, W1r, 0, 1);
    // layer 2: h0 -> h1
    gather_kernel<<<gather_blocks, 256>>>(x, 1);
    node_kernel<<<node_blocks, 256>>>(x, W2l, b2, W2r, 1, 2);
    // layer 3: h1 -> h0
    gather_kernel<<<gather_blocks, 256>>>(x, 2);
    node_kernel<<<node_blocks, 256>>>(x, W3l, b3, W3r, 2, 1);

    // pool + head
    pool_kernel<<<(NN + 255) / 256, 256>>>(batch);
    head_kernel<<<1, 64>>>(Wc1, bc1, Wc2, bc2, out);
}

// round 9
// speedup vs baseline: 1.1202x; 1.1202x over previous
#include <cuda_runtime.h>

#define NN 100000
#define NE 1600000
#define CH 64
#define NG 64
#define SCAN_BS 1024
#define SCAN_NB ((NN + SCAN_BS - 1) / SCAN_BS)   // 98
#define NB_M 1563                                 // 64-node GEMM tiles
#define NB_G 12500                                // gather blocks (8 nodes each)
#define GRID_A (NB_M * 9)                         // 14067 interleaved blocks

// ---------------- device scratch (no allocation allowed) ----------------
__device__ __align__(16) float g_agg[NN * CH];
__device__ __align__(16) float g_tmp[NN * CH];
__device__ __align__(16) float g_h0[NN * CH];
__device__ __align__(16) float g_h1[NN * CH];
__device__ float g_inv[NN];
__device__ int   g_deg[NN];
__device__ int   g_off[NN];
__device__ int   g_fill[NN];
__device__ int   g_srcl[NE];
__device__ int   g_bsum[SCAN_NB];
__device__ float g_pool[NG * CH];
__device__ float g_pcnt[NG];
__device__ int   g_is64_ei;
__device__ int   g_is64_b;

// ---------------- init: zero deg/pool + dtype detect ----------------
// int64 little-endian with values < 2^31 => odd 32-bit words are zero.
// Probe indices are in-bounds for BOTH int32 and int64 layouts.
__global__ void init_kernel(const int* __restrict__ ei32, const int* __restrict__ b32) {
    int i = blockIdx.x * blockDim.x + threadIdx.x;
    if (i < NN) g_deg[i] = 0;
    if (blockIdx.x == 0) {
        for (int j = threadIdx.x; j < NG * CH; j += blockDim.x) g_pool[j] = 0.f;
        if (threadIdx.x < NG) g_pcnt[threadIdx.x] = 0.f;
        if (threadIdx.x == 0) {
            int oe = 0, ob = 0;
#pragma unroll 1
            for (int t = 0; t < 64; t++) oe |= ei32[2 * (t * 24999 + 7) + 1];
#pragma unroll 1
            for (int t = 0; t < 64; t++) ob |= b32[2 * (t * 780 + 3) + 1];
            g_is64_ei = (oe == 0) ? 1 : 0;
            g_is64_b  = (ob == 0) ? 1 : 0;
        }
    }
}

// ---------------- CSR build ----------------
__global__ void deg_kernel(const int* __restrict__ ei) {
    int e = blockIdx.x * blockDim.x + threadIdx.x;
    if (e < NE) {
        int d = g_is64_ei ? ei[2 * (NE + e)] : ei[NE + e];
        atomicAdd(&g_deg[d], 1);
    }
}
__global__ void scan1_kernel() {
    __shared__ int s[SCAN_BS];
    int t = threadIdx.x;
    int gid = blockIdx.x * SCAN_BS + t;
    int v = (gid < NN) ? g_deg[gid] : 0;
    s[t] = v;
    __syncthreads();
    for (int off = 1; off < SCAN_BS; off <<= 1) {
        int x = (t >= off) ? s[t - off] : 0;
        __syncthreads();
        s[t] += x;
        __syncthreads();
    }
    if (gid < NN) g_off[gid] = s[t] - v;        // exclusive within block
    if (t == SCAN_BS - 1) g_bsum[blockIdx.x] = s[t];
}
__global__ void scan2b_kernel() {
    __shared__ int s[128];
    __shared__ int base_s;
    int t = threadIdx.x;
    if (t < 128) s[t] = (t < (int)blockIdx.x && t < SCAN_NB) ? g_bsum[t] : 0;
    __syncthreads();
    if (t < 64) s[t] += s[t + 64];
    __syncthreads();
    if (t < 32) {
        int v = s[t] + s[t + 32];
        for (int o = 16; o > 0; o >>= 1) v += __shfl_down_sync(0xffffffffu, v, o);
        if (t == 0) base_s = v;
    }
    __syncthreads();
    int gid = blockIdx.x * SCAN_BS + t;
    if (gid < NN) {
        int o = g_off[gid] + base_s;
        g_off[gid] = o;
        g_fill[gid] = o;
        g_inv[gid] = 1.0f / fmaxf((float)g_deg[gid], 1.0f);
    }
}
__global__ void fill_kernel(const int* __restrict__ ei) {
    int e = blockIdx.x * blockDim.x + threadIdx.x;
    if (e < NE) {
        int is64 = g_is64_ei;
        int s = is64 ? ei[2 * e]        : ei[e];
        int d = is64 ? ei[2 * (NE + e)] : ei[NE + e];
        g_srcl[atomicAdd(&g_fill[d], 1)] = s;
    }
}

// ---------------- phase A: gather (agg) OVERLAPPED with tmp = X@Wr + b ----------------
// Interleaved block roles (1 GEMM : 8 gather) so FFMA-bound GEMM blocks fill the
// L2-latency stalls of gather blocks on every SM. X@Wr is independent of agg.
__global__ void __launch_bounds__(256) phaseA_kernel(const float* __restrict__ Xext,
                                                     const float* __restrict__ Wr,
                                                     const float* __restrict__ bvec,
                                                     int srcsel) {
    const float* __restrict__ X = (srcsel == 0) ? Xext : (srcsel == 1 ? g_h0 : g_h1);

    __shared__ float Ws[64][64];   // 16 KB
    __shared__ float Ac[64][33];   // 8.45 KB
    __shared__ float bs[64];

    int b = blockIdx.x;
    int q = b / 9, r = b - q * 9;
    int tid = threadIdx.x;

    if (r == 0) {
        // ================= GEMM role: tmp[tile q] = X@Wr + b =================
        int nbase = q * 64;
        for (int i = tid; i < 64 * 64; i += 256) Ws[i >> 6][i & 63] = Wr[i];
        if (tid < 64) bs[tid] = bvec[tid];

        int tx = tid & 15;   // cols 4*tx..4*tx+3
        int ty = tid >> 4;   // nodes 4*ty..4*ty+3

        float acc[4][4];
#pragma unroll
        for (int i = 0; i < 4; i++)
#pragma unroll
            for (int j = 0; j < 4; j++) acc[i][j] = 0.f;

        for (int c = 0; c < 2; c++) {
            __syncthreads();
            {
                int k = tid & 31;
                int n0 = tid >> 5;
                int koff = c * 32;
#pragma unroll
                for (int nn = n0; nn < 64; nn += 8) {
                    int n = nbase + nn;
                    Ac[nn][k] = (n < NN) ? X[(size_t)n * CH + koff + k] : 0.f;
                }
            }
            __syncthreads();
#pragma unroll 8
            for (int kk = 0; kk < 32; kk++) {
                float4 w = *(const float4*)&Ws[c * 32 + kk][tx * 4];
#pragma unroll
                for (int i = 0; i < 4; i++) {
                    float a = Ac[ty * 4 + i][kk];
                    acc[i][0] += a * w.x;
                    acc[i][1] += a * w.y;
                    acc[i][2] += a * w.z;
                    acc[i][3] += a * w.w;
                }
            }
        }
#pragma unroll
        for (int i = 0; i < 4; i++) {
            int n = nbase + ty * 4 + i;
            if (n < NN) {
                float4 o;
                o.x = acc[i][0] + bs[tx * 4 + 0];
                o.y = acc[i][1] + bs[tx * 4 + 1];
                o.z = acc[i][2] + bs[tx * 4 + 2];
                o.w = acc[i][3] + bs[tx * 4 + 3];
                *(float4*)&g_tmp[(size_t)n * CH + tx * 4] = o;
            }
        }
    } else {
        // ================= gather role: agg = mean_{src} X[src] =================
        int gi = b - q - 1;                       // gather block index
        int node = gi * 8 + (tid >> 5);
        int lane = tid & 31;
        if (gi >= NB_G || node >= NN) return;
        int beg = g_off[node];
        int deg = g_deg[node];
        float a0 = 0.f, a1 = 0.f;
        int j = 0;
        for (; j + 2 <= deg; j += 2) {
            int s0 = g_srcl[beg + j];
            int s1 = g_srcl[beg + j + 1];
            const float* r0 = X + (size_t)s0 * CH;
            const float* r1 = X + (size_t)s1 * CH;
            a0 += r0[lane] + r1[lane];
            a1 += r0[lane + 32] + r1[lane + 32];
        }
        if (j < deg) {
            const float* r0 = X + (size_t)g_srcl[beg + j] * CH;
            a0 += r0[lane];
            a1 += r0[lane + 32];
        }
        float iv = g_inv[node];
        g_agg[(size_t)node * CH + lane]      = a0 * iv;
        g_agg[(size_t)node * CH + lane + 32] = a1 * iv;
    }
}

// ---------------- phase B: Y = relu(agg @ Wl + tmp) ----------------
__global__ void __launch_bounds__(256) phaseB_kernel(const float* __restrict__ Wl,
                                                     int dstsel) {
    float* __restrict__ Yout = (dstsel == 1) ? g_h0 : g_h1;

    __shared__ float Ws[64][64];   // 16 KB
    __shared__ float Ac[64][33];   // 8.45 KB

    int tid = threadIdx.x;
    int nbase = blockIdx.x * 64;

    for (int i = tid; i < 64 * 64; i += 256) Ws[i >> 6][i & 63] = Wl[i];

    int tx = tid & 15;
    int ty = tid >> 4;

    float acc[4][4];
#pragma unroll
    for (int i = 0; i < 4; i++)
#pragma unroll
        for (int j = 0; j < 4; j++) acc[i][j] = 0.f;

    for (int c = 0; c < 2; c++) {
        __syncthreads();
        {
            int k = tid & 31;
            int n0 = tid >> 5;
            int koff = c * 32;
#pragma unroll
            for (int nn = n0; nn < 64; nn += 8) {
                int n = nbase + nn;
                Ac[nn][k] = (n < NN) ? g_agg[(size_t)n * CH + koff + k] : 0.f;
            }
        }
        __syncthreads();
#pragma unroll 8
        for (int kk = 0; kk < 32; kk++) {
            float4 w = *(const float4*)&Ws[c * 32 + kk][tx * 4];
#pragma unroll
            for (int i = 0; i < 4; i++) {
                float a = Ac[ty * 4 + i][kk];
                acc[i][0] += a * w.x;
                acc[i][1] += a * w.y;
                acc[i][2] += a * w.z;
                acc[i][3] += a * w.w;
            }
        }
    }

#pragma unroll
    for (int i = 0; i < 4; i++) {
        int n = nbase + ty * 4 + i;
        if (n < NN) {
            float4 t = *(const float4*)&g_tmp[(size_t)n * CH + tx * 4];
            float4 o;
            o.x = fmaxf(acc[i][0] + t.x, 0.f);
            o.y = fmaxf(acc[i][1] + t.y, 0.f);
            o.z = fmaxf(acc[i][2] + t.z, 0.f);
            o.w = fmaxf(acc[i][3] + t.w, 0.f);
            *(float4*)&Yout[(size_t)n * CH + tx * 4] = o;
        }
    }
}

// ---------------- pooling (batch is sorted) ----------------
__global__ void __launch_bounds__(256) pool_kernel(const int* __restrict__ batch) {
    int is64 = g_is64_b;
    const float* H = g_h0;   // final layer output lives in g_h0
    int c = threadIdx.x & 63;
    int rg = threadIdx.x >> 6;
    int r0 = blockIdx.x * 256 + rg * 64;
    float acc = 0.f, cacc = 0.f;
    int cur = -1;
    for (int i = 0; i < 64; i++) {
        int r = r0 + i;
        if (r >= NN) break;
        int g = is64 ? batch[2 * r] : batch[r];
        if (g != cur) {
            if (cur >= 0) {
                atomicAdd(&g_pool[cur * CH + c], acc);
                if (c == 0) atomicAdd(&g_pcnt[cur], cacc);
            }
            cur = g; acc = 0.f; cacc = 0.f;
        }
        acc += H[(size_t)r * CH + c];
        cacc += 1.f;
    }
    if (cur >= 0) {
        atomicAdd(&g_pool[cur * CH + c], acc);
        if (c == 0) atomicAdd(&g_pcnt[cur], cacc);
    }
}

// ---------------- MLP head ----------------
__global__ void head_kernel(const float* __restrict__ Wc1, const float* __restrict__ bc1,
                            const float* __restrict__ Wc2, const float* __restrict__ bc2,
                            float* __restrict__ out) {
    int g = threadIdx.x;
    if (g >= NG) return;
    float iv = 1.0f / fmaxf(g_pcnt[g], 1.0f);
    float gv[64];
#pragma unroll
    for (int k = 0; k < 64; k++) gv[k] = g_pool[g * CH + k] * iv;
    float o0 = bc2[0], o1 = bc2[1];
    for (int j = 0; j < 32; j++) {
        float h = bc1[j];
#pragma unroll
        for (int k = 0; k < 64; k++) h += gv[k] * Wc1[k * 32 + j];
        h = fmaxf(h, 0.f);
        o0 += h * Wc2[j * 2 + 0];
        o1 += h * Wc2[j * 2 + 1];
    }
    out[g * 2 + 0] = o0;
    out[g * 2 + 1] = o1;
}

extern "C" void kernel_launch(void* const* d_in, const int* in_sizes, int n_in,
                              void* d_out, int out_size) {
    (void)in_sizes; (void)n_in; (void)out_size;
    const float* x   = (const float*)d_in[0];
    const int* ei    = (const int*)d_in[1];    // width auto-detected on device
    const int* batch = (const int*)d_in[2];
    const float* W1l = (const float*)d_in[3];
    const float* b1  = (const float*)d_in[4];
    const float* W1r = (const float*)d_in[5];
    const float* W2l = (const float*)d_in[6];
    const float* b2  = (const float*)d_in[7];
    const float* W2r = (const float*)d_in[8];
    const float* W3l = (const float*)d_in[9];
    const float* b3  = (const float*)d_in[10];
    const float* W3r = (const float*)d_in[11];
    const float* Wc1 = (const float*)d_in[12];
    const float* bc1 = (const float*)d_in[13];
    const float* Wc2 = (const float*)d_in[14];
    const float* bc2 = (const float*)d_in[15];
    float* out = (float*)d_out;

    const int ZB = 256;

    // CSR build (5 launches)
    init_kernel<<<(NN + ZB - 1) / ZB, ZB>>>(ei, batch);
    deg_kernel<<<(NE + ZB - 1) / ZB, ZB>>>(ei);
    scan1_kernel<<<SCAN_NB, SCAN_BS>>>();
    scan2b_kernel<<<SCAN_NB, SCAN_BS>>>();
    fill_kernel<<<(NE + ZB - 1) / ZB, ZB>>>(ei);

    // layer 1: x -> h0
    phaseA_kernel<<<GRID_A, 256>>>(x, W1r, b1, 0);
    phaseB_kernel<<<NB_M, 256>>>(W1l, 1);
    // layer 2: h0 -> h1
    phaseA_kernel<<<GRID_A, 256>>>(x, W2r, b2, 1);
    phaseB_kernel<<<NB_M, 256>>>(W2l, 2);
    // layer 3: h1 -> h0
    phaseA_kernel<<<GRID_A, 256>>>(x, W3r, b3, 2);
    phaseB_kernel<<<NB_M, 256>>>(W3l, 1);

    // pool + head
    pool_kernel<<<(NN + 255) / 256, 256>>>(batch);
    head_kernel<<<1, 64>>>(Wc1, bc1, Wc2, bc2, out);
}

// round 10
// speedup vs baseline: 1.2687x; 1.1326x over previous
#include <cuda_runtime.h>

#define NN 100000
#define NE 1600000
#define CH 64
#define NG 64
#define SCAN_BS 1024
#define SCAN_NB ((NN + SCAN_BS - 1) / SCAN_BS)   // 98

// ---------------- device scratch (no allocation allowed) ----------------
__device__ __align__(16) float g_agg[NN * CH];
__device__ __align__(16) float g_h0[NN * CH];
__device__ __align__(16) float g_h1[NN * CH];
__device__ float g_inv[NN];
__device__ int   g_deg[NN];
__device__ int   g_off[NN];
__device__ int   g_fill[NN];
__device__ int   g_srcl[NE];
__device__ int   g_bsum[SCAN_NB];
__device__ float g_pool[NG * CH];
__device__ float g_pcnt[NG];
__device__ int   g_is64_ei;
__device__ int   g_is64_b;

// ---------------- init: zero deg/pool + dtype detect ----------------
// int64 little-endian with values < 2^31 => odd 32-bit words are zero.
// Probe indices are in-bounds for BOTH int32 and int64 layouts.
__global__ void init_kernel(const int* __restrict__ ei32, const int* __restrict__ b32) {
    int i = blockIdx.x * blockDim.x + threadIdx.x;
    if (i < NN) g_deg[i] = 0;
    if (blockIdx.x == 0) {
        for (int j = threadIdx.x; j < NG * CH; j += blockDim.x) g_pool[j] = 0.f;
        if (threadIdx.x < NG) g_pcnt[threadIdx.x] = 0.f;
        if (threadIdx.x == 0) {
            int oe = 0, ob = 0;
#pragma unroll 1
            for (int t = 0; t < 64; t++) oe |= ei32[2 * (t * 24999 + 7) + 1];
#pragma unroll 1
            for (int t = 0; t < 64; t++) ob |= b32[2 * (t * 780 + 3) + 1];
            g_is64_ei = (oe == 0) ? 1 : 0;
            g_is64_b  = (ob == 0) ? 1 : 0;
        }
    }
}

// ---------------- CSR build ----------------
__global__ void deg_kernel(const int* __restrict__ ei) {
    int e = blockIdx.x * blockDim.x + threadIdx.x;
    if (e < NE) {
        int d = g_is64_ei ? ei[2 * (NE + e)] : ei[NE + e];
        atomicAdd(&g_deg[d], 1);
    }
}
__global__ void scan1_kernel() {
    __shared__ int s[SCAN_BS];
    int t = threadIdx.x;
    int gid = blockIdx.x * SCAN_BS + t;
    int v = (gid < NN) ? g_deg[gid] : 0;
    s[t] = v;
    __syncthreads();
    for (int off = 1; off < SCAN_BS; off <<= 1) {
        int x = (t >= off) ? s[t - off] : 0;
        __syncthreads();
        s[t] += x;
        __syncthreads();
    }
    if (gid < NN) g_off[gid] = s[t] - v;        // exclusive within block
    if (t == SCAN_BS - 1) g_bsum[blockIdx.x] = s[t];
}
// per-block base via reduction of preceding block sums; also fills inv + fill-cursor
__global__ void scan2b_kernel() {
    __shared__ int s[128];
    __shared__ int base_s;
    int t = threadIdx.x;
    if (t < 128) s[t] = (t < (int)blockIdx.x && t < SCAN_NB) ? g_bsum[t] : 0;
    __syncthreads();
    if (t < 64) s[t] += s[t + 64];
    __syncthreads();
    if (t < 32) {
        int v = s[t] + s[t + 32];
        for (int o = 16; o > 0; o >>= 1) v += __shfl_down_sync(0xffffffffu, v, o);
        if (t == 0) base_s = v;
    }
    __syncthreads();
    int gid = blockIdx.x * SCAN_BS + t;
    if (gid < NN) {
        int o = g_off[gid] + base_s;
        g_off[gid] = o;
        g_fill[gid] = o;
        g_inv[gid] = 1.0f / fmaxf((float)g_deg[gid], 1.0f);
    }
}
__global__ void fill_kernel(const int* __restrict__ ei) {
    int e = blockIdx.x * blockDim.x + threadIdx.x;
    if (e < NE) {
        int is64 = g_is64_ei;
        int s = is64 ? ei[2 * e]        : ei[e];
        int d = is64 ? ei[2 * (NE + e)] : ei[NE + e];
        g_srcl[atomicAdd(&g_fill[d], 1)] = s;
    }
}

// ---------------- aggregation via gather: LDG.64 lanes + 4-edge unroll ----------------
// warp per dst node; lane owns channels 2*lane, 2*lane+1 (one float2 per row).
// Fuses mean (inv). Same per-channel addition order as before -> same numerics.
__global__ void __launch_bounds__(256) gather_kernel(const float* __restrict__ Xext,
                                                     int srcsel) {
    const float* __restrict__ X = (srcsel == 0) ? Xext : (srcsel == 1 ? g_h0 : g_h1);
    int warp = (blockIdx.x * blockDim.x + threadIdx.x) >> 5;
    if (warp >= NN) return;
    int lane = threadIdx.x & 31;
    int co = lane * 2;                 // channel offset for this lane
    int beg = g_off[warp];
    int deg = g_deg[warp];

    float a0 = 0.f, a1 = 0.f;
    int j = 0;
    for (; j + 4 <= deg; j += 4) {
        int s0 = g_srcl[beg + j];
        int s1 = g_srcl[beg + j + 1];
        int s2 = g_srcl[beg + j + 2];
        int s3 = g_srcl[beg + j + 3];
        float2 v0 = *(const float2*)(X + (size_t)s0 * CH + co);
        float2 v1 = *(const float2*)(X + (size_t)s1 * CH + co);
        float2 v2 = *(const float2*)(X + (size_t)s2 * CH + co);
        float2 v3 = *(const float2*)(X + (size_t)s3 * CH + co);
        a0 += v0.x + v1.x + v2.x + v3.x;
        a1 += v0.y + v1.y + v2.y + v3.y;
    }
    for (; j < deg; j++) {
        float2 v = *(const float2*)(X + (size_t)g_srcl[beg + j] * CH + co);
        a0 += v.x;
        a1 += v.y;
    }
    float iv = g_inv[warp];
    *(float2*)(g_agg + (size_t)warp * CH + co) = make_float2(a0 * iv, a1 * iv);
}

// ---------------- node transform (R2-proven) ----------------
// Y = relu([agg | X] @ [Wl;Wr] + b). 64-node tile, 256 threads, 4x4 micro-tile,
// k-chunked A in shared (~41.5KB total smem).
__global__ void __launch_bounds__(256) node_kernel(const float* __restrict__ Xext,
                                                   const float* __restrict__ Wl,
                                                   const float* __restrict__ bvec,
                                                   const float* __restrict__ Wr,
                                                   int srcsel, int dstsel) {
    const float* __restrict__ Xin = (srcsel == 0) ? Xext : (srcsel == 1 ? g_h0 : g_h1);
    float* __restrict__ Yout = (dstsel == 1) ? g_h0 : g_h1;

    __shared__ float Ws[128][64];   // rows 0..63 = Wl, 64..127 = Wr (32 KB)
    __shared__ float Ac[64][33];    // 64-node x 32-k chunk (8.45 KB)
    __shared__ float bs[64];

    int tid = threadIdx.x;
    int nbase = blockIdx.x * 64;

    for (int i = tid; i < 64 * 64; i += 256) {
        int k = i >> 6, j = i & 63;
        Ws[k][j]      = Wl[i];
        Ws[k + 64][j] = Wr[i];
    }
    if (tid < 64) bs[tid] = bvec[tid];

    int tx = tid & 15;   // output cols 4*tx..4*tx+3
    int ty = tid >> 4;   // rows 4*ty..4*ty+3

    float acc[4][4];
#pragma unroll
    for (int i = 0; i < 4; i++)
#pragma unroll
        for (int j = 0; j < 4; j++) acc[i][j] = 0.f;

    for (int c = 0; c < 4; c++) {
        __syncthreads();
        {
            int k = tid & 31;
            int n0 = tid >> 5;
            const float* __restrict__ S = (c < 2) ? g_agg : Xin;
            int koff = (c & 1) * 32;
#pragma unroll
            for (int nn = n0; nn < 64; nn += 8) {
                int n = nbase + nn;
                Ac[nn][k] = (n < NN) ? S[(size_t)n * CH + koff + k] : 0.f;
            }
        }
        __syncthreads();
        int kb = c * 32;
#pragma unroll 8
        for (int kk = 0; kk < 32; kk++) {
            float4 w = *(const float4*)&Ws[kb + kk][tx * 4];
#pragma unroll
            for (int i = 0; i < 4; i++) {
                float a = Ac[ty * 4 + i][kk];
                acc[i][0] += a * w.x;
                acc[i][1] += a * w.y;
                acc[i][2] += a * w.z;
                acc[i][3] += a * w.w;
            }
        }
    }

#pragma unroll
    for (int i = 0; i < 4; i++) {
        int n = nbase + ty * 4 + i;
        if (n < NN) {
            float4 o;
            o.x = fmaxf(acc[i][0] + bs[tx * 4 + 0], 0.f);
            o.y = fmaxf(acc[i][1] + bs[tx * 4 + 1], 0.f);
            o.z = fmaxf(acc[i][2] + bs[tx * 4 + 2], 0.f);
            o.w = fmaxf(acc[i][3] + bs[tx * 4 + 3], 0.f);
            *(float4*)&Yout[(size_t)n * CH + tx * 4] = o;
        }
    }
}

// ---------------- pooling (batch is sorted) ----------------
__global__ void __launch_bounds__(256) pool_kernel(const int* __restrict__ batch) {
    int is64 = g_is64_b;
    const float* H = g_h0;   // final layer output lives in g_h0
    int c = threadIdx.x & 63;
    int rg = threadIdx.x >> 6;
    int r0 = blockIdx.x * 256 + rg * 64;
    float acc = 0.f, cacc = 0.f;
    int cur = -1;
    for (int i = 0; i < 64; i++) {
        int r = r0 + i;
        if (r >= NN) break;
        int g = is64 ? batch[2 * r] : batch[r];
        if (g != cur) {
            if (cur >= 0) {
                atomicAdd(&g_pool[cur * CH + c], acc);
                if (c == 0) atomicAdd(&g_pcnt[cur], cacc);
            }
            cur = g; acc = 0.f; cacc = 0.f;
        }
        acc += H[(size_t)r * CH + c];
        cacc += 1.f;
    }
    if (cur >= 0) {
        atomicAdd(&g_pool[cur * CH + c], acc);
        if (c == 0) atomicAdd(&g_pcnt[cur], cacc);
    }
}

// ---------------- MLP head ----------------
__global__ void head_kernel(const float* __restrict__ Wc1, const float* __restrict__ bc1,
                            const float* __restrict__ Wc2, const float* __restrict__ bc2,
                            float* __restrict__ out) {
    int g = threadIdx.x;
    if (g >= NG) return;
    float iv = 1.0f / fmaxf(g_pcnt[g], 1.0f);
    float gv[64];
#pragma unroll
    for (int k = 0; k < 64; k++) gv[k] = g_pool[g * CH + k] * iv;
    float o0 = bc2[0], o1 = bc2[1];
    for (int j = 0; j < 32; j++) {
        float h = bc1[j];
#pragma unroll
        for (int k = 0; k < 64; k++) h += gv[k] * Wc1[k * 32 + j];
        h = fmaxf(h, 0.f);
        o0 += h * Wc2[j * 2 + 0];
        o1 += h * Wc2[j * 2 + 1];
    }
    out[g * 2 + 0] = o0;
    out[g * 2 + 1] = o1;
}

extern "C" void kernel_launch(void* const* d_in, const int* in_sizes, int n_in,
                              void* d_out, int out_size) {
    (void)in_sizes; (void)n_in; (void)out_size;
    const float* x   = (const float*)d_in[0];
    const int* ei    = (const int*)d_in[1];    // width auto-detected on device
    const int* batch = (const int*)d_in[2];
    const float* W1l = (const float*)d_in[3];
    const float* b1  = (const float*)d_in[4];
    const float* W1r = (const float*)d_in[5];
    const float* W2l = (const float*)d_in[6];
    const float* b2  = (const float*)d_in[7];
    const float* W2r = (const float*)d_in[8];
    const float* W3l = (const float*)d_in[9];
    const float* b3  = (const float*)d_in[10];
    const float* W3r = (const float*)d_in[11];
    const float* Wc1 = (const float*)d_in[12];
    const float* bc1 = (const float*)d_in[13];
    const float* Wc2 = (const float*)d_in[14];
    const float* bc2 = (const float*)d_in[15];
    float* out = (float*)d_out;

    const int ZB = 256;
    const int gather_blocks = (NN * 32 + 255) / 256;   // warp per node
    const int node_blocks   = (NN + 63) / 64;

    // CSR build (5 launches)
    init_kernel<<<(NN + ZB - 1) / ZB, ZB>>>(ei, batch);
    deg_kernel<<<(NE + ZB - 1) / ZB, ZB>>>(ei);
    scan1_kernel<<<SCAN_NB, SCAN_BS>>>();
    scan2b_kernel<<<SCAN_NB, SCAN_BS>>>();
    fill_kernel<<<(NE + ZB - 1) / ZB, ZB>>>(ei);

    // layer 1: x -> h0
    gather_kernel<<<gather_blocks, 256>>>(x, 0);
    node_kernel<<<node_blocks, 256>>>(x, W1l, b1, W1r, 0, 1);
    // layer 2: h0 -> h1
    gather_kernel<<<gather_blocks, 256>>>(x, 1);
    node_kernel<<<node_blocks, 256>>>(x, W2l, b2, W2r, 1, 2);
    // layer 3: h1 -> h0
    gather_kernel<<<gather_blocks, 256>>>(x, 2);
    node_kernel<<<node_blocks, 256>>>(x, W3l, b3, W3r, 2, 1);

    // pool + head
    pool_kernel<<<(NN + 255) / 256, 256>>>(batch);
    head_kernel<<<1, 64>>>(Wc1, bc1, Wc2, bc2, out);
}